// round 9
// baseline (speedup 1.0000x reference)
#include <cuda_runtime.h>
#include <cstdint>

// Conv2d N=32, Cin=64, 64x64, Cout=128, 3x3 s1 p1, fp32.
// Implicit GEMM on mma.sync.m16n8k8.tf32.
// R9 = R8 + double-buffered software pipeline over 4 half-chunks of 16 ci:
// prefetch(c+1) is issued before draining buffer c (cp.async.wait_group 1),
// hiding staging latency behind the tap-loop compute. Compute inner loop is
// R4-verbatim (scalar LDS a-frags) with 2 s-steps per half-chunk.

#define HW  64
#define CO  128
#define CIN 64

#define SB_ROW   264
#define SB_HALF  (72 * SB_ROW)            // 19008 floats per half-chunk B
#define SA_CI    424                      // 6*66=396 data + pad; 8 mod 32
#define SA_HALF  (16 * SA_CI)             // 6784 floats per half-chunk A
#define BUF_FL   (SB_HALF + SA_HALF)      // 25792 floats per buffer
#define SMEM_BYTES (2 * BUF_FL * 4)       // 206,336 B

__device__ __align__(16) float g_bimg[4 * SB_HALF];

__device__ __forceinline__ uint32_t f2tf32(float f) {
    uint32_t r; asm("cvt.rna.tf32.f32 %0, %1;" : "=r"(r) : "f"(f)); return r;
}
__device__ __forceinline__ void mma8(float c[4], const uint32_t a[4], uint2 b) {
    asm volatile(
        "mma.sync.aligned.m16n8k8.row.col.f32.tf32.tf32.f32 "
        "{%0,%1,%2,%3}, {%4,%5,%6,%7}, {%8,%9}, {%0,%1,%2,%3};"
        : "+f"(c[0]), "+f"(c[1]), "+f"(c[2]), "+f"(c[3])
        : "r"(a[0]), "r"(a[1]), "r"(a[2]), "r"(a[3]), "r"(b.x), "r"(b.y));
}
__device__ __forceinline__ uint32_t smem_u32(const void* p) {
    uint32_t a;
    asm("{ .reg .u64 t; cvta.to.shared.u64 t, %1; cvt.u32.u64 %0, t; }"
        : "=r"(a) : "l"(p));
    return a;
}

// Half-chunk B image: g_bimg[half][rowp = tap*8 + s2*4 + j][2*co + slot]
// slot0 = w[k], slot1 = w[k+4], k = s2*8 + j (0..11), ci = half*16 + k.
__global__ void __launch_bounds__(256)
prep_b(const float* __restrict__ w)
{
    int e  = blockIdx.x * 256 + threadIdx.x;    // 0..36863
    int co = e & 127;
    int rp = e >> 7;                            // 0..287 = half*72 + rowp
    int half = rp / 72;
    int rowp = rp - half * 72;
    int tap = rowp >> 3;
    int s2  = (rowp >> 2) & 1;
    int jj  = rowp & 3;
    int k   = s2 * 8 + jj;
    const float* wb = w + (size_t)(half * 16) * 9 * CO;
    float2 pv;
    pv.x = __uint_as_float(f2tf32(wb[((size_t)k * 9 + tap) * CO + co]));
    pv.y = __uint_as_float(f2tf32(wb[((size_t)(k + 4) * 9 + tap) * CO + co]));
    *(float2*)&g_bimg[(size_t)rp * SB_ROW + 2 * co] = pv;
}

__device__ __forceinline__ void stage_half(const float* __restrict__ in,
                                           uint32_t sbase, int buf, int half,
                                           int n, int y0, int tid)
{
    const uint32_t bbase = sbase + (uint32_t)(buf * BUF_FL) * 4u;

    // ---- A via cp.async (4B, zfill OOB), raw fp32 ----
    const float* inb = in + ((size_t)n * CIN + half * 16) * (HW * HW);
    for (int e = tid; e < 16 * 396; e += 512) {
        int p   = e / 66;               // cil*6 + row
        int col = e - p * 66;
        int cil = p / 6;
        int row = p - cil * 6;
        int gy  = y0 - 1 + row;
        int gx  = col - 1;
        bool ok = ((unsigned)gy < (unsigned)HW) && ((unsigned)gx < (unsigned)HW);
        const float* src = inb + ((size_t)cil * HW + (ok ? gy : 0)) * HW
                               + (ok ? gx : 0);
        uint32_t dst = bbase + (uint32_t)(SB_HALF + cil * SA_CI + row * 66 + col) * 4u;
        uint32_t sz  = ok ? 4u : 0u;
        asm volatile("cp.async.ca.shared.global [%0], [%1], 4, %2;"
                     :: "r"(dst), "l"(src), "r"(sz) : "memory");
    }

    // ---- B via cp.async (16B) from prebuilt image ----
    const float* bimg = g_bimg + (size_t)half * SB_HALF;
    for (int e = tid; e < 72 * 66; e += 512) {
        int rowp = e / 66;
        int g    = e - rowp * 66;
        uint32_t dst = bbase + (uint32_t)(rowp * SB_ROW) * 4u + (uint32_t)g * 16u;
        const float* src = bimg + (size_t)rowp * SB_ROW + g * 4;
        asm volatile("cp.async.cg.shared.global [%0], [%1], 16;"
                     :: "r"(dst), "l"(src) : "memory");
    }
    asm volatile("cp.async.commit_group;" ::: "memory");
}

__global__ void __launch_bounds__(512, 1)
conv_mma_kernel(const float* __restrict__ in, const float* __restrict__ bias,
                float* __restrict__ out)
{
    extern __shared__ float sm[];
    const uint32_t sbase = smem_u32(sm);

    const int tid   = threadIdx.x;
    const int lane  = tid & 31;
    const int warp  = tid >> 5;
    const int wy    = warp >> 2;        // 0..3 -> y row within tile
    const int warpN = warp & 3;         // 0..3 -> co 32-block
    const int y0    = blockIdx.x * 4;
    const int n     = blockIdx.y;

    const int r = lane >> 2;            // 0..7
    const int j = lane & 3;             // 0..3

    float acc[4][4][4];
#pragma unroll
    for (int mt = 0; mt < 4; ++mt)
#pragma unroll
        for (int nt = 0; nt < 4; ++nt)
#pragma unroll
            for (int q = 0; q < 4; ++q) acc[mt][nt][q] = 0.f;

    stage_half(in, sbase, 0, 0, n, y0, tid);

    for (int c = 0; c < 4; ++c) {
        const int buf = c & 1;

        if (c < 3)
            stage_half(in, sbase, buf ^ 1, c + 1, n, y0, tid);

        if (c < 3)
            asm volatile("cp.async.wait_group 1;" ::: "memory");
        else
            asm volatile("cp.async.wait_group 0;" ::: "memory");

        // ---- in-place tf32 convert of this buffer's A region ----
        const uint32_t abase = sbase + (uint32_t)(buf * BUF_FL + SB_HALF) * 4u;
        for (int e = tid; e < SA_HALF; e += 512) {
            uint32_t ad = abase + (uint32_t)e * 4u;
            float v;
            asm volatile("ld.shared.f32 %0, [%1];" : "=f"(v) : "r"(ad));
            uint32_t t = f2tf32(v);
            asm volatile("st.shared.b32 [%0], %1;" :: "r"(ad), "r"(t) : "memory");
        }
        __syncthreads();

        // ---- compute: 9 taps x 2 ksteps, warp tile 64x32 (R4-style) ----
        const float* smA = sm + buf * BUF_FL + SB_HALF;
        const float* smB = sm + buf * BUF_FL;
#pragma unroll
        for (int tap = 0; tap < 9; ++tap) {
            const int dy = tap / 3 - 1;
            const int dx = tap % 3 - 1;
            const float* pA = &smA[j * SA_CI + (wy + dy + 1) * 66 + 1 + dx + r];
            const float* pB = &smB[(tap * 8 + j) * SB_ROW + 2 * (warpN * 32 + r)];
#pragma unroll
            for (int s = 0; s < 2; ++s) {
                const float* pAs = pA + s * 8 * SA_CI;
                uint32_t a[4][4];
#pragma unroll
                for (int mt = 0; mt < 4; ++mt) {
                    a[mt][0] = __float_as_uint(pAs[mt * 16]);
                    a[mt][1] = __float_as_uint(pAs[mt * 16 + 8]);
                    a[mt][2] = __float_as_uint(pAs[mt * 16 + 4 * SA_CI]);
                    a[mt][3] = __float_as_uint(pAs[mt * 16 + 8 + 4 * SA_CI]);
                }
                const float* pBs = pB + s * 4 * SB_ROW;
#pragma unroll
                for (int nt = 0; nt < 4; ++nt) {
                    uint2 b = *(const uint2*)&pBs[nt * 16];
#pragma unroll
                    for (int mt = 0; mt < 4; ++mt)
                        mma8(acc[mt][nt], a[mt], b);
                }
            }
        }
        __syncthreads();   // all reads of buf done before it is refilled
    }

    // ---- epilogue: c frag rows (r, r+8), cols (2j, 2j+1) ----
    const int y = y0 + wy;
#pragma unroll
    for (int nt = 0; nt < 4; ++nt) {
        int co = warpN * 32 + nt * 8 + 2 * j;
        float b0 = __ldg(bias + co);
        float b1 = __ldg(bias + co + 1);
        float* o0 = out + (((size_t)n * CO + co) * HW + y) * HW;
#pragma unroll
        for (int mt = 0; mt < 4; ++mt) {
            int x = mt * 16 + r;
            o0[x]               = acc[mt][nt][0] + b0;
            o0[HW * HW + x]     = acc[mt][nt][1] + b1;
            o0[x + 8]           = acc[mt][nt][2] + b0;
            o0[HW * HW + x + 8] = acc[mt][nt][3] + b1;
        }
    }
}

extern "C" void kernel_launch(void* const* d_in, const int* in_sizes, int n_in,
                              void* d_out, int out_size)
{
    const float* in   = (const float*)d_in[0];
    const float* w    = (const float*)d_in[1];
    const float* bias = (const float*)d_in[2];
    float* out        = (float*)d_out;

    prep_b<<<144, 256>>>(w);

    cudaFuncSetAttribute(conv_mma_kernel,
                         cudaFuncAttributeMaxDynamicSharedMemorySize, SMEM_BYTES);
    dim3 grid(16, 32);
    conv_mma_kernel<<<grid, 512, SMEM_BYTES>>>(in, bias, out);
}

// round 11
// speedup vs baseline: 1.0520x; 1.0520x over previous
#include <cuda_runtime.h>
#include <cstdint>

// Conv2d N=32, Cin=64, 64x64, Cout=128, 3x3 s1 p1, fp32.
// Implicit GEMM on mma.sync.m16n8k8.tf32.
// R11 = R10 with the A staging/convert loop bound fixed (e < SAQ; R10's
// "SAQ - 2*66" left 132 floats/quarter unstaged -> rel_err 0.25).
// 2 co-resident CTAs/SM (256 thr, M=128 = 2y x 64x, N=128), 1024 CTAs
// (6.92/SM -> 1.2% tail). K in 8 quarter-chunks of 8 ci, double-buffered
// cp.async staging; compute loop R4-verbatim, one k-step per tap.

#define HW  64
#define CO  128
#define CIN 64

#define SB_ROW  264
#define SBQ     (36 * SB_ROW)             // 9504 floats: B quarter (9 taps x 4 j-rows)
#define SA_CI   264                       // 4 rows x 66 cols; 264 = 8 mod 32
#define SAQ     (8 * SA_CI)               // 2112 floats: A quarter (8 ci)
#define BUF_FL  (SBQ + SAQ)               // 11616 floats per buffer
#define SMEM_BYTES (2 * BUF_FL * 4)       // 92,928 B -> 2 CTAs/SM

__device__ __align__(16) float g_bimg[8 * SBQ];

__device__ __forceinline__ uint32_t f2tf32(float f) {
    uint32_t r; asm("cvt.rna.tf32.f32 %0, %1;" : "=r"(r) : "f"(f)); return r;
}
__device__ __forceinline__ void mma8(float c[4], const uint32_t a[4], uint2 b) {
    asm volatile(
        "mma.sync.aligned.m16n8k8.row.col.f32.tf32.tf32.f32 "
        "{%0,%1,%2,%3}, {%4,%5,%6,%7}, {%8,%9}, {%0,%1,%2,%3};"
        : "+f"(c[0]), "+f"(c[1]), "+f"(c[2]), "+f"(c[3])
        : "r"(a[0]), "r"(a[1]), "r"(a[2]), "r"(a[3]), "r"(b.x), "r"(b.y));
}
__device__ __forceinline__ uint32_t smem_u32(const void* p) {
    uint32_t a;
    asm("{ .reg .u64 t; cvta.to.shared.u64 t, %1; cvt.u32.u64 %0, t; }"
        : "=r"(a) : "l"(p));
    return a;
}

// Quarter B image: g_bimg[q][rowp = tap*4 + j][2*co + slot]
// slot0 = w[ci = q*8 + j], slot1 = w[ci = q*8 + j + 4], tf32-rounded.
__global__ void __launch_bounds__(256)
prep_b(const float* __restrict__ w)
{
    int e  = blockIdx.x * 256 + threadIdx.x;    // 0..36863
    int co = e & 127;
    int rp = e >> 7;                            // 0..287 = q*36 + rowp
    int q    = rp / 36;
    int rowp = rp - q * 36;
    int tap  = rowp >> 2;
    int jj   = rowp & 3;
    int ci0  = q * 8 + jj;
    float2 pv;
    pv.x = __uint_as_float(f2tf32(w[((size_t)ci0 * 9 + tap) * CO + co]));
    pv.y = __uint_as_float(f2tf32(w[((size_t)(ci0 + 4) * 9 + tap) * CO + co]));
    *(float2*)&g_bimg[(size_t)rp * SB_ROW + 2 * co] = pv;
}

__device__ __forceinline__ void stage_quarter(const float* __restrict__ in,
                                              uint32_t sbase, int buf, int q,
                                              int n, int y0, int tid)
{
    const uint32_t bbase = sbase + (uint32_t)(buf * BUF_FL) * 4u;

    // ---- A via cp.async (4B, zfill OOB): 8 ci x 4 rows x 66 cols ----
    const float* inb = in + ((size_t)n * CIN + q * 8) * (HW * HW);
    for (int e = tid; e < SAQ; e += 256) {
        int p   = e / 66;               // ci*4 + row
        int col = e - p * 66;
        int ci  = p >> 2;
        int row = p & 3;
        int gy  = y0 - 1 + row;
        int gx  = col - 1;
        bool ok = ((unsigned)gy < (unsigned)HW) && ((unsigned)gx < (unsigned)HW);
        const float* src = inb + ((size_t)ci * HW + (ok ? gy : 0)) * HW
                               + (ok ? gx : 0);
        uint32_t dst = bbase + (uint32_t)(SBQ + ci * SA_CI + row * 66 + col) * 4u;
        uint32_t sz  = ok ? 4u : 0u;
        asm volatile("cp.async.ca.shared.global [%0], [%1], 4, %2;"
                     :: "r"(dst), "l"(src), "r"(sz) : "memory");
    }

    // ---- B via cp.async (16B) from prebuilt quarter image ----
    const float* bimg = g_bimg + (size_t)q * SBQ;
    for (int e = tid; e < 36 * 66; e += 256) {
        int rowp = e / 66;
        int g    = e - rowp * 66;
        uint32_t dst = bbase + (uint32_t)(rowp * SB_ROW) * 4u + (uint32_t)g * 16u;
        const float* src = bimg + (size_t)rowp * SB_ROW + g * 4;
        asm volatile("cp.async.cg.shared.global [%0], [%1], 16;"
                     :: "r"(dst), "l"(src) : "memory");
    }
    asm volatile("cp.async.commit_group;" ::: "memory");
}

__global__ void __launch_bounds__(256, 2)
conv_mma_kernel(const float* __restrict__ in, const float* __restrict__ bias,
                float* __restrict__ out)
{
    extern __shared__ float sm[];
    const uint32_t sbase = smem_u32(sm);

    const int tid   = threadIdx.x;
    const int lane  = tid & 31;
    const int warp  = tid >> 5;
    const int wy    = warp >> 2;        // 0..1 -> y row within tile
    const int warpN = warp & 3;         // 0..3 -> co 32-block
    const int y0    = blockIdx.x * 2;
    const int n     = blockIdx.y;

    const int r = lane >> 2;            // 0..7
    const int j = lane & 3;             // 0..3

    float acc[4][4][4];
#pragma unroll
    for (int mt = 0; mt < 4; ++mt)
#pragma unroll
        for (int nt = 0; nt < 4; ++nt)
#pragma unroll
            for (int q = 0; q < 4; ++q) acc[mt][nt][q] = 0.f;

    stage_quarter(in, sbase, 0, 0, n, y0, tid);

    for (int q = 0; q < 8; ++q) {
        const int buf = q & 1;

        if (q < 7)
            stage_quarter(in, sbase, buf ^ 1, q + 1, n, y0, tid);

        if (q < 7)
            asm volatile("cp.async.wait_group 1;" ::: "memory");
        else
            asm volatile("cp.async.wait_group 0;" ::: "memory");
        __syncthreads();

        // ---- in-place tf32 convert of this buffer's A region ----
        const uint32_t abase = sbase + (uint32_t)(buf * BUF_FL + SBQ) * 4u;
        for (int e = tid; e < SAQ; e += 256) {
            uint32_t ad = abase + (uint32_t)e * 4u;
            float v;
            asm volatile("ld.shared.f32 %0, [%1];" : "=f"(v) : "r"(ad));
            uint32_t t = f2tf32(v);
            asm volatile("st.shared.b32 [%0], %1;" :: "r"(ad), "r"(t) : "memory");
        }
        __syncthreads();

        // ---- compute: 9 taps x 1 kstep, warp tile 64x32 (R4-style) ----
        const float* smA = sm + buf * BUF_FL + SBQ;
        const float* smB = sm + buf * BUF_FL;
#pragma unroll
        for (int tap = 0; tap < 9; ++tap) {
            const int dy = tap / 3 - 1;
            const int dx = tap % 3 - 1;
            const float* pAs = &smA[j * SA_CI + (wy + dy + 1) * 66 + 1 + dx + r];
            const float* pBs = &smB[(tap * 4 + j) * SB_ROW + 2 * (warpN * 32 + r)];
            uint32_t a[4][4];
#pragma unroll
            for (int mt = 0; mt < 4; ++mt) {
                a[mt][0] = __float_as_uint(pAs[mt * 16]);
                a[mt][1] = __float_as_uint(pAs[mt * 16 + 8]);
                a[mt][2] = __float_as_uint(pAs[mt * 16 + 4 * SA_CI]);
                a[mt][3] = __float_as_uint(pAs[mt * 16 + 8 + 4 * SA_CI]);
            }
#pragma unroll
            for (int nt = 0; nt < 4; ++nt) {
                uint2 b = *(const uint2*)&pBs[nt * 16];
#pragma unroll
                for (int mt = 0; mt < 4; ++mt)
                    mma8(acc[mt][nt], a[mt], b);
            }
        }
        __syncthreads();   // all reads of buf done before it is refilled
    }

    // ---- epilogue: c frag rows (r, r+8), cols (2j, 2j+1) ----
    const int y = y0 + wy;
#pragma unroll
    for (int nt = 0; nt < 4; ++nt) {
        int co = warpN * 32 + nt * 8 + 2 * j;
        float b0 = __ldg(bias + co);
        float b1 = __ldg(bias + co + 1);
        float* o0 = out + (((size_t)n * CO + co) * HW + y) * HW;
#pragma unroll
        for (int mt = 0; mt < 4; ++mt) {
            int x = mt * 16 + r;
            o0[x]               = acc[mt][nt][0] + b0;
            o0[HW * HW + x]     = acc[mt][nt][1] + b1;
            o0[x + 8]           = acc[mt][nt][2] + b0;
            o0[HW * HW + x + 8] = acc[mt][nt][3] + b1;
        }
    }
}

extern "C" void kernel_launch(void* const* d_in, const int* in_sizes, int n_in,
                              void* d_out, int out_size)
{
    const float* in   = (const float*)d_in[0];
    const float* w    = (const float*)d_in[1];
    const float* bias = (const float*)d_in[2];
    float* out        = (float*)d_out;

    prep_b<<<144, 256>>>(w);

    cudaFuncSetAttribute(conv_mma_kernel,
                         cudaFuncAttributeMaxDynamicSharedMemorySize, SMEM_BYTES);
    dim3 grid(32, 32);
    conv_mma_kernel<<<grid, 256, SMEM_BYTES>>>(in, bias, out);
}

// round 12
// speedup vs baseline: 1.1646x; 1.1070x over previous
#include <cuda_runtime.h>
#include <cstdint>

// Conv2d N=32, Cin=64, 64x64, Cout=128, 3x3 s1 p1, fp32.
// Implicit GEMM on mma.sync.m16n8k8.tf32.
// R12 = R11 minus staging ALU:
//   - B copy is linear (B image rows are packed: 264 floats = 66 x 16B).
//   - A smem dst is linear (SA_CI = 4*66); divisions only for src coords.
//   - NO A tf32-convert sweep: raw fp32 bits fed to mma.tf32 (HW reads the
//     upper 19 bits -> truncation). B stays rna-rounded in prep_b.
// 2 CTAs/SM (256 thr, M=128, N=128), 1024 CTAs, 8 double-buffered quarters.

#define HW  64
#define CO  128
#define CIN 64

#define SB_ROW  264
#define SBQ     (36 * SB_ROW)             // 9504 floats: B quarter (9 taps x 4 j-rows)
#define SA_CI   264                       // 4 rows x 66 cols; 264 = 8 mod 32
#define SAQ     (8 * SA_CI)               // 2112 floats: A quarter (8 ci)
#define BUF_FL  (SBQ + SAQ)               // 11616 floats per buffer
#define SMEM_BYTES (2 * BUF_FL * 4)       // 92,928 B -> 2 CTAs/SM

__device__ __align__(16) float g_bimg[8 * SBQ];

__device__ __forceinline__ uint32_t f2tf32(float f) {
    uint32_t r; asm("cvt.rna.tf32.f32 %0, %1;" : "=r"(r) : "f"(f)); return r;
}
__device__ __forceinline__ void mma8(float c[4], const uint32_t a[4], uint2 b) {
    asm volatile(
        "mma.sync.aligned.m16n8k8.row.col.f32.tf32.tf32.f32 "
        "{%0,%1,%2,%3}, {%4,%5,%6,%7}, {%8,%9}, {%0,%1,%2,%3};"
        : "+f"(c[0]), "+f"(c[1]), "+f"(c[2]), "+f"(c[3])
        : "r"(a[0]), "r"(a[1]), "r"(a[2]), "r"(a[3]), "r"(b.x), "r"(b.y));
}
__device__ __forceinline__ uint32_t smem_u32(const void* p) {
    uint32_t a;
    asm("{ .reg .u64 t; cvta.to.shared.u64 t, %1; cvt.u32.u64 %0, t; }"
        : "=r"(a) : "l"(p));
    return a;
}

// Quarter B image: g_bimg[q][rowp = tap*4 + j][2*co + slot]
// slot0 = w[ci = q*8 + j], slot1 = w[ci = q*8 + j + 4], tf32(rna)-rounded.
__global__ void __launch_bounds__(256)
prep_b(const float* __restrict__ w)
{
    int e  = blockIdx.x * 256 + threadIdx.x;    // 0..36863
    int co = e & 127;
    int rp = e >> 7;                            // 0..287 = q*36 + rowp
    int q    = rp / 36;
    int rowp = rp - q * 36;
    int tap  = rowp >> 2;
    int jj   = rowp & 3;
    int ci0  = q * 8 + jj;
    float2 pv;
    pv.x = __uint_as_float(f2tf32(w[((size_t)ci0 * 9 + tap) * CO + co]));
    pv.y = __uint_as_float(f2tf32(w[((size_t)(ci0 + 4) * 9 + tap) * CO + co]));
    *(float2*)&g_bimg[(size_t)rp * SB_ROW + 2 * co] = pv;
}

__device__ __forceinline__ void stage_quarter(const float* __restrict__ in,
                                              uint32_t sbase, int buf, int q,
                                              int n, int y0, int tid)
{
    const uint32_t bbase = sbase + (uint32_t)(buf * BUF_FL) * 4u;

    // ---- A via cp.async (4B, zfill OOB): 8 ci x 4 rows x 66 cols.
    //      dst is linear (SA_CI = 4*66); divisions only for src coords. ----
    const float* inb = in + ((size_t)n * CIN + q * 8) * (HW * HW);
    for (int e = tid; e < SAQ; e += 256) {
        int p   = e / 66;               // ci*4 + row
        int col = e - p * 66;
        int ci  = p >> 2;
        int row = p & 3;
        int gy  = y0 - 1 + row;
        int gx  = col - 1;
        bool ok = ((unsigned)gy < (unsigned)HW) && ((unsigned)gx < (unsigned)HW);
        const float* src = inb + ((size_t)ci * HW + (ok ? gy : 0)) * HW
                               + (ok ? gx : 0);
        uint32_t dst = bbase + (uint32_t)(SBQ + e) * 4u;
        uint32_t sz  = ok ? 4u : 0u;
        asm volatile("cp.async.ca.shared.global [%0], [%1], 4, %2;"
                     :: "r"(dst), "l"(src), "r"(sz) : "memory");
    }

    // ---- B via cp.async (16B), fully linear: image rows are packed ----
    const float* bimg = g_bimg + (size_t)q * SBQ;
    for (int e = tid; e < SBQ / 4; e += 256) {      // 2376 x 16B chunks
        uint32_t dst = bbase + (uint32_t)e * 16u;
        const float* src = bimg + (size_t)e * 4;
        asm volatile("cp.async.cg.shared.global [%0], [%1], 16;"
                     :: "r"(dst), "l"(src) : "memory");
    }
    asm volatile("cp.async.commit_group;" ::: "memory");
}

__global__ void __launch_bounds__(256, 2)
conv_mma_kernel(const float* __restrict__ in, const float* __restrict__ bias,
                float* __restrict__ out)
{
    extern __shared__ float sm[];
    const uint32_t sbase = smem_u32(sm);

    const int tid   = threadIdx.x;
    const int lane  = tid & 31;
    const int warp  = tid >> 5;
    const int wy    = warp >> 2;        // 0..1 -> y row within tile
    const int warpN = warp & 3;         // 0..3 -> co 32-block
    const int y0    = blockIdx.x * 2;
    const int n     = blockIdx.y;

    const int r = lane >> 2;            // 0..7
    const int j = lane & 3;             // 0..3

    float acc[4][4][4];
#pragma unroll
    for (int mt = 0; mt < 4; ++mt)
#pragma unroll
        for (int nt = 0; nt < 4; ++nt)
#pragma unroll
            for (int q = 0; q < 4; ++q) acc[mt][nt][q] = 0.f;

    stage_quarter(in, sbase, 0, 0, n, y0, tid);

    for (int q = 0; q < 8; ++q) {
        const int buf = q & 1;

        if (q < 7)
            stage_quarter(in, sbase, buf ^ 1, q + 1, n, y0, tid);

        if (q < 7)
            asm volatile("cp.async.wait_group 1;" ::: "memory");
        else
            asm volatile("cp.async.wait_group 0;" ::: "memory");
        __syncthreads();

        // ---- compute: 9 taps x 1 kstep, warp tile 64x32 (R4-style).
        //      A is raw fp32; mma.tf32 reads the upper 19 bits. ----
        const float* smA = sm + buf * BUF_FL + SBQ;
        const float* smB = sm + buf * BUF_FL;
#pragma unroll
        for (int tap = 0; tap < 9; ++tap) {
            const int dy = tap / 3 - 1;
            const int dx = tap % 3 - 1;
            const float* pAs = &smA[j * SA_CI + (wy + dy + 1) * 66 + 1 + dx + r];
            const float* pBs = &smB[(tap * 4 + j) * SB_ROW + 2 * (warpN * 32 + r)];
            uint32_t a[4][4];
#pragma unroll
            for (int mt = 0; mt < 4; ++mt) {
                a[mt][0] = __float_as_uint(pAs[mt * 16]);
                a[mt][1] = __float_as_uint(pAs[mt * 16 + 8]);
                a[mt][2] = __float_as_uint(pAs[mt * 16 + 4 * SA_CI]);
                a[mt][3] = __float_as_uint(pAs[mt * 16 + 8 + 4 * SA_CI]);
            }
#pragma unroll
            for (int nt = 0; nt < 4; ++nt) {
                uint2 b = *(const uint2*)&pBs[nt * 16];
#pragma unroll
                for (int mt = 0; mt < 4; ++mt)
                    mma8(acc[mt][nt], a[mt], b);
            }
        }
        __syncthreads();   // all reads of buf done before it is refilled
    }

    // ---- epilogue: c frag rows (r, r+8), cols (2j, 2j+1) ----
    const int y = y0 + wy;
#pragma unroll
    for (int nt = 0; nt < 4; ++nt) {
        int co = warpN * 32 + nt * 8 + 2 * j;
        float b0 = __ldg(bias + co);
        float b1 = __ldg(bias + co + 1);
        float* o0 = out + (((size_t)n * CO + co) * HW + y) * HW;
#pragma unroll
        for (int mt = 0; mt < 4; ++mt) {
            int x = mt * 16 + r;
            o0[x]               = acc[mt][nt][0] + b0;
            o0[HW * HW + x]     = acc[mt][nt][1] + b1;
            o0[x + 8]           = acc[mt][nt][2] + b0;
            o0[HW * HW + x + 8] = acc[mt][nt][3] + b1;
        }
    }
}

extern "C" void kernel_launch(void* const* d_in, const int* in_sizes, int n_in,
                              void* d_out, int out_size)
{
    const float* in   = (const float*)d_in[0];
    const float* w    = (const float*)d_in[1];
    const float* bias = (const float*)d_in[2];
    float* out        = (float*)d_out;

    prep_b<<<144, 256>>>(w);

    cudaFuncSetAttribute(conv_mma_kernel,
                         cudaFuncAttributeMaxDynamicSharedMemorySize, SMEM_BYTES);
    dim3 grid(32, 32);
    conv_mma_kernel<<<grid, 256, SMEM_BYTES>>>(in, bias, out);
}

// round 13
// speedup vs baseline: 1.2102x; 1.0392x over previous
#include <cuda_runtime.h>
#include <cstdint>

// Conv2d N=32, Cin=64, 64x64, Cout=128, 3x3 s1 p1, fp32.
// Implicit GEMM on mma.sync.m16n8k8.tf32.
// R13 = R12 with staging pressure removed:
//   - B never goes through smem: b-frags LDG.64 directly from the prep_b
//     image (fragment-layout, 38KB/quarter, L1-resident; cp.async.cg for A
//     bypasses L1 so it stays resident).
//   - A staged as 16B cp.async (rows 256B-aligned in gmem); new smem layout
//     row stride 76 (16B aligned), ci stride 312 (=24 mod 32 -> banks 24j+r
//     conflict-free). x-halo cols (-1, 64) are always zero: zeroed once.
// 2 CTAs/SM (256 thr, M=128, N=128), 1024 CTAs, 8 double-buffered quarters.

#define HW  64
#define CO  128
#define CIN 64

#define SB_ROW     264
#define SBQ        (36 * SB_ROW)          // 9504 floats per B quarter image
#define ROW_STRIDE 76                     // floats; 304B, 16B aligned
#define CI_STRIDE  312                    // floats; 24 mod 32; 1248B, 16B aligned
#define SAQ        (8 * CI_STRIDE)        // 2496 floats per A quarter buffer
#define SMEM_BYTES (2 * SAQ * 4)          // 19,968 B

__device__ __align__(16) float g_bimg[8 * SBQ];

__device__ __forceinline__ uint32_t f2tf32(float f) {
    uint32_t r; asm("cvt.rna.tf32.f32 %0, %1;" : "=r"(r) : "f"(f)); return r;
}
__device__ __forceinline__ void mma8(float c[4], const uint32_t a[4], uint2 b) {
    asm volatile(
        "mma.sync.aligned.m16n8k8.row.col.f32.tf32.tf32.f32 "
        "{%0,%1,%2,%3}, {%4,%5,%6,%7}, {%8,%9}, {%0,%1,%2,%3};"
        : "+f"(c[0]), "+f"(c[1]), "+f"(c[2]), "+f"(c[3])
        : "r"(a[0]), "r"(a[1]), "r"(a[2]), "r"(a[3]), "r"(b.x), "r"(b.y));
}
__device__ __forceinline__ uint32_t smem_u32(const void* p) {
    uint32_t a;
    asm("{ .reg .u64 t; cvta.to.shared.u64 t, %1; cvt.u32.u64 %0, t; }"
        : "=r"(a) : "l"(p));
    return a;
}

// Quarter B image: g_bimg[q][rowp = tap*4 + j][2*co + slot]
// slot0 = w[ci = q*8 + j], slot1 = w[ci = q*8 + j + 4], tf32(rna)-rounded.
__global__ void __launch_bounds__(256)
prep_b(const float* __restrict__ w)
{
    int e  = blockIdx.x * 256 + threadIdx.x;    // 0..36863
    int co = e & 127;
    int rp = e >> 7;                            // 0..287 = q*36 + rowp
    int q    = rp / 36;
    int rowp = rp - q * 36;
    int tap  = rowp >> 2;
    int jj   = rowp & 3;
    int ci0  = q * 8 + jj;
    float2 pv;
    pv.x = __uint_as_float(f2tf32(w[((size_t)ci0 * 9 + tap) * CO + co]));
    pv.y = __uint_as_float(f2tf32(w[((size_t)(ci0 + 4) * 9 + tap) * CO + co]));
    *(float2*)&g_bimg[(size_t)rp * SB_ROW + 2 * co] = pv;
}

// Stage A quarter: 8 ci x 4 rows x 64 cols as 16B cp.async (zfill OOB rows).
__device__ __forceinline__ void stage_quarter(const float* __restrict__ in,
                                              uint32_t sbase, int buf, int q,
                                              int n, int y0, int tid)
{
    const uint32_t abase = sbase + (uint32_t)(buf * SAQ) * 4u;
    const float* inb = in + ((size_t)n * CIN + q * 8) * (HW * HW);
#pragma unroll
    for (int it = 0; it < 2; ++it) {
        int e   = it * 256 + tid;       // 0..511
        int p   = e >> 4;               // ci*4 + row
        int k   = e & 15;               // 16B chunk within row
        int ci  = p >> 2;
        int row = p & 3;
        int gy  = y0 - 1 + row;
        bool ok = (unsigned)gy < (unsigned)HW;
        const float* src = inb + (((size_t)ci << 6) + (ok ? gy : 0)) * HW + (k << 2);
        uint32_t dst = abase
                     + (uint32_t)(ci * CI_STRIDE + row * ROW_STRIDE + 4 + (k << 2)) * 4u;
        uint32_t sz  = ok ? 16u : 0u;
        asm volatile("cp.async.cg.shared.global [%0], [%1], 16, %2;"
                     :: "r"(dst), "l"(src), "r"(sz) : "memory");
    }
    asm volatile("cp.async.commit_group;" ::: "memory");
}

__global__ void __launch_bounds__(256, 2)
conv_mma_kernel(const float* __restrict__ in, const float* __restrict__ bias,
                float* __restrict__ out)
{
    extern __shared__ float sm[];
    const uint32_t sbase = smem_u32(sm);

    const int tid   = threadIdx.x;
    const int lane  = tid & 31;
    const int warp  = tid >> 5;
    const int wy    = warp >> 2;        // 0..1 -> y row within tile
    const int warpN = warp & 3;         // 0..3 -> co 32-block
    const int y0    = blockIdx.x * 2;
    const int n     = blockIdx.y;

    const int r = lane >> 2;            // 0..7
    const int j = lane & 3;             // 0..3

    // Zero the x-halo words (col -1 at off 3, col 64 at off 68) once, both bufs.
    if (tid < 128) {
        int buf  = tid >> 6;
        int rem  = tid & 63;
        int ci   = rem >> 3;
        int row  = (rem >> 1) & 3;
        int side = rem & 1;
        sm[buf * SAQ + ci * CI_STRIDE + row * ROW_STRIDE + (side ? 68 : 3)] = 0.f;
    }

    float acc[4][4][4];
#pragma unroll
    for (int mt = 0; mt < 4; ++mt)
#pragma unroll
        for (int nt = 0; nt < 4; ++nt)
#pragma unroll
            for (int qq = 0; qq < 4; ++qq) acc[mt][nt][qq] = 0.f;

    stage_quarter(in, sbase, 0, 0, n, y0, tid);

    for (int q = 0; q < 8; ++q) {
        const int buf = q & 1;

        if (q < 7)
            stage_quarter(in, sbase, buf ^ 1, q + 1, n, y0, tid);

        if (q < 7)
            asm volatile("cp.async.wait_group 1;" ::: "memory");
        else
            asm volatile("cp.async.wait_group 0;" ::: "memory");
        __syncthreads();

        // ---- compute: 9 taps x 1 kstep; A from smem, B LDG from g_bimg ----
        const float* smA = sm + buf * SAQ;
        const float* __restrict__ bq = g_bimg + (size_t)q * SBQ;
#pragma unroll
        for (int tap = 0; tap < 9; ++tap) {
            const int dy = tap / 3 - 1;
            const int dx = tap % 3 - 1;
            const float* pAs = &smA[j * CI_STRIDE + (wy + dy + 1) * ROW_STRIDE
                                    + 4 + dx + r];
            const float* __restrict__ pBs =
                bq + (tap * 4 + j) * SB_ROW + 2 * (warpN * 32 + r);
            uint32_t a[4][4];
#pragma unroll
            for (int mt = 0; mt < 4; ++mt) {
                a[mt][0] = __float_as_uint(pAs[mt * 16]);
                a[mt][1] = __float_as_uint(pAs[mt * 16 + 8]);
                a[mt][2] = __float_as_uint(pAs[mt * 16 + 4 * CI_STRIDE]);
                a[mt][3] = __float_as_uint(pAs[mt * 16 + 8 + 4 * CI_STRIDE]);
            }
#pragma unroll
            for (int nt = 0; nt < 4; ++nt) {
                uint2 b = *(const uint2*)&pBs[nt * 16];
#pragma unroll
                for (int mt = 0; mt < 4; ++mt)
                    mma8(acc[mt][nt], a[mt], b);
            }
        }
        __syncthreads();   // all reads of buf done before it is refilled
    }

    // ---- epilogue: c frag rows (r, r+8), cols (2j, 2j+1) ----
    const int y = y0 + wy;
#pragma unroll
    for (int nt = 0; nt < 4; ++nt) {
        int co = warpN * 32 + nt * 8 + 2 * j;
        float b0 = __ldg(bias + co);
        float b1 = __ldg(bias + co + 1);
        float* o0 = out + (((size_t)n * CO + co) * HW + y) * HW;
#pragma unroll
        for (int mt = 0; mt < 4; ++mt) {
            int x = mt * 16 + r;
            o0[x]               = acc[mt][nt][0] + b0;
            o0[HW * HW + x]     = acc[mt][nt][1] + b1;
            o0[x + 8]           = acc[mt][nt][2] + b0;
            o0[HW * HW + x + 8] = acc[mt][nt][3] + b1;
        }
    }
}

extern "C" void kernel_launch(void* const* d_in, const int* in_sizes, int n_in,
                              void* d_out, int out_size)
{
    const float* in   = (const float*)d_in[0];
    const float* w    = (const float*)d_in[1];
    const float* bias = (const float*)d_in[2];
    float* out        = (float*)d_out;

    prep_b<<<144, 256>>>(w);

    cudaFuncSetAttribute(conv_mma_kernel,
                         cudaFuncAttributeMaxDynamicSharedMemorySize, SMEM_BYTES);
    dim3 grid(32, 32);
    conv_mma_kernel<<<grid, 256, SMEM_BYTES>>>(in, bias, out);
}

// round 14
// speedup vs baseline: 1.2908x; 1.0666x over previous
#include <cuda_runtime.h>
#include <cstdint>

// Conv2d N=32, Cin=64, 64x64, Cout=128, 3x3 s1 p1, fp32.
// Implicit GEMM on mma.sync.m16n8k8.tf32.
// R14 = R13 with K chunks coarsened from 8 ci to 16 ci (quarters -> halves):
// barriers per CTA drop 16 -> 8, pipeline iters 8 -> 4, each compute region
// doubles (more cover for the prefetch). B stays direct-LDG from the prep_b
// image (row block 2h+s for half h, kstep s). A smem double buffer 40KB/CTA,
// still 2 CTAs/SM (reg-bound).

#define HW  64
#define CO  128
#define CIN 64

#define SB_ROW     264
#define SBQ        (36 * SB_ROW)          // 9504 floats per B quarter image
#define ROW_STRIDE 76                     // floats; 304B, 16B aligned
#define CI_STRIDE  312                    // floats; 24 mod 32; conflict-free
#define SAH        (16 * CI_STRIDE)       // 4992 floats per A half buffer
#define SMEM_BYTES (2 * SAH * 4)          // 39,936 B -> 2 CTAs/SM

__device__ __align__(16) float g_bimg[8 * SBQ];

__device__ __forceinline__ uint32_t f2tf32(float f) {
    uint32_t r; asm("cvt.rna.tf32.f32 %0, %1;" : "=r"(r) : "f"(f)); return r;
}
__device__ __forceinline__ void mma8(float c[4], const uint32_t a[4], uint2 b) {
    asm volatile(
        "mma.sync.aligned.m16n8k8.row.col.f32.tf32.tf32.f32 "
        "{%0,%1,%2,%3}, {%4,%5,%6,%7}, {%8,%9}, {%0,%1,%2,%3};"
        : "+f"(c[0]), "+f"(c[1]), "+f"(c[2]), "+f"(c[3])
        : "r"(a[0]), "r"(a[1]), "r"(a[2]), "r"(a[3]), "r"(b.x), "r"(b.y));
}
__device__ __forceinline__ uint32_t smem_u32(const void* p) {
    uint32_t a;
    asm("{ .reg .u64 t; cvta.to.shared.u64 t, %1; cvt.u32.u64 %0, t; }"
        : "=r"(a) : "l"(p));
    return a;
}

// Quarter B image: g_bimg[q][rowp = tap*4 + j][2*co + slot]
// slot0 = w[ci = q*8 + j], slot1 = w[ci = q*8 + j + 4], tf32(rna)-rounded.
__global__ void __launch_bounds__(256)
prep_b(const float* __restrict__ w)
{
    int e  = blockIdx.x * 256 + threadIdx.x;    // 0..36863
    int co = e & 127;
    int rp = e >> 7;                            // 0..287 = q*36 + rowp
    int q    = rp / 36;
    int rowp = rp - q * 36;
    int tap  = rowp >> 2;
    int jj   = rowp & 3;
    int ci0  = q * 8 + jj;
    float2 pv;
    pv.x = __uint_as_float(f2tf32(w[((size_t)ci0 * 9 + tap) * CO + co]));
    pv.y = __uint_as_float(f2tf32(w[((size_t)(ci0 + 4) * 9 + tap) * CO + co]));
    *(float2*)&g_bimg[(size_t)rp * SB_ROW + 2 * co] = pv;
}

// Stage A half: 16 ci x 4 rows x 64 cols as 16B cp.async (zfill OOB rows).
__device__ __forceinline__ void stage_half(const float* __restrict__ in,
                                           uint32_t sbase, int buf, int h,
                                           int n, int y0, int tid)
{
    const uint32_t abase = sbase + (uint32_t)(buf * SAH) * 4u;
    const float* inb = in + ((size_t)n * CIN + h * 16) * (HW * HW);
#pragma unroll
    for (int it = 0; it < 4; ++it) {
        int e   = it * 256 + tid;       // 0..1023
        int p   = e >> 4;               // ci*4 + row
        int k   = e & 15;               // 16B chunk within row
        int ci  = p >> 2;
        int row = p & 3;
        int gy  = y0 - 1 + row;
        bool ok = (unsigned)gy < (unsigned)HW;
        const float* src = inb + (((size_t)ci << 6) + (ok ? gy : 0)) * HW + (k << 2);
        uint32_t dst = abase
                     + (uint32_t)(ci * CI_STRIDE + row * ROW_STRIDE + 4 + (k << 2)) * 4u;
        uint32_t sz  = ok ? 16u : 0u;
        asm volatile("cp.async.cg.shared.global [%0], [%1], 16, %2;"
                     :: "r"(dst), "l"(src), "r"(sz) : "memory");
    }
    asm volatile("cp.async.commit_group;" ::: "memory");
}

__global__ void __launch_bounds__(256, 2)
conv_mma_kernel(const float* __restrict__ in, const float* __restrict__ bias,
                float* __restrict__ out)
{
    extern __shared__ float sm[];
    const uint32_t sbase = smem_u32(sm);

    const int tid   = threadIdx.x;
    const int lane  = tid & 31;
    const int warp  = tid >> 5;
    const int wy    = warp >> 2;        // 0..1 -> y row within tile
    const int warpN = warp & 3;         // 0..3 -> co 32-block
    const int y0    = blockIdx.x * 2;
    const int n     = blockIdx.y;

    const int r = lane >> 2;            // 0..7
    const int j = lane & 3;             // 0..3

    // Zero x-halo words (col -1 at off 3, col 64 at off 68): 16ci x 4row x
    // 2side x 2buf = 256 words, one per thread.
    {
        int buf  = tid >> 7;
        int rem  = tid & 127;
        int ci   = rem >> 3;
        int row  = (rem >> 1) & 3;
        int side = rem & 1;
        sm[buf * SAH + ci * CI_STRIDE + row * ROW_STRIDE + (side ? 68 : 3)] = 0.f;
    }

    float acc[4][4][4];
#pragma unroll
    for (int mt = 0; mt < 4; ++mt)
#pragma unroll
        for (int nt = 0; nt < 4; ++nt)
#pragma unroll
            for (int qq = 0; qq < 4; ++qq) acc[mt][nt][qq] = 0.f;

    stage_half(in, sbase, 0, 0, n, y0, tid);

    for (int h = 0; h < 4; ++h) {
        const int buf = h & 1;

        if (h < 3)
            stage_half(in, sbase, buf ^ 1, h + 1, n, y0, tid);

        if (h < 3)
            asm volatile("cp.async.wait_group 1;" ::: "memory");
        else
            asm volatile("cp.async.wait_group 0;" ::: "memory");
        __syncthreads();

        // ---- compute: 9 taps x 2 ksteps; A from smem, B LDG from g_bimg ----
        const float* smA = sm + buf * SAH;
        const float* __restrict__ bh = g_bimg + (size_t)(h * 2) * SBQ;
#pragma unroll
        for (int tap = 0; tap < 9; ++tap) {
            const int dy = tap / 3 - 1;
            const int dx = tap % 3 - 1;
            const float* pA = &smA[j * CI_STRIDE + (wy + dy + 1) * ROW_STRIDE
                                   + 4 + dx + r];
            const float* __restrict__ pB =
                bh + (tap * 4 + j) * SB_ROW + 2 * (warpN * 32 + r);
#pragma unroll
            for (int s = 0; s < 2; ++s) {
                const float* pAs = pA + s * 8 * CI_STRIDE;
                const float* __restrict__ pBs = pB + s * SBQ;
                uint32_t a[4][4];
#pragma unroll
                for (int mt = 0; mt < 4; ++mt) {
                    a[mt][0] = __float_as_uint(pAs[mt * 16]);
                    a[mt][1] = __float_as_uint(pAs[mt * 16 + 8]);
                    a[mt][2] = __float_as_uint(pAs[mt * 16 + 4 * CI_STRIDE]);
                    a[mt][3] = __float_as_uint(pAs[mt * 16 + 8 + 4 * CI_STRIDE]);
                }
#pragma unroll
                for (int nt = 0; nt < 4; ++nt) {
                    uint2 b = *(const uint2*)&pBs[nt * 16];
#pragma unroll
                    for (int mt = 0; mt < 4; ++mt)
                        mma8(acc[mt][nt], a[mt], b);
                }
            }
        }
        __syncthreads();   // all reads of buf done before it is refilled
    }

    // ---- epilogue: c frag rows (r, r+8), cols (2j, 2j+1) ----
    const int y = y0 + wy;
#pragma unroll
    for (int nt = 0; nt < 4; ++nt) {
        int co = warpN * 32 + nt * 8 + 2 * j;
        float b0 = __ldg(bias + co);
        float b1 = __ldg(bias + co + 1);
        float* o0 = out + (((size_t)n * CO + co) * HW + y) * HW;
#pragma unroll
        for (int mt = 0; mt < 4; ++mt) {
            int x = mt * 16 + r;
            o0[x]               = acc[mt][nt][0] + b0;
            o0[HW * HW + x]     = acc[mt][nt][1] + b1;
            o0[x + 8]           = acc[mt][nt][2] + b0;
            o0[HW * HW + x + 8] = acc[mt][nt][3] + b1;
        }
    }
}

extern "C" void kernel_launch(void* const* d_in, const int* in_sizes, int n_in,
                              void* d_out, int out_size)
{
    const float* in   = (const float*)d_in[0];
    const float* w    = (const float*)d_in[1];
    const float* bias = (const float*)d_in[2];
    float* out        = (float*)d_out;

    prep_b<<<144, 256>>>(w);

    cudaFuncSetAttribute(conv_mma_kernel,
                         cudaFuncAttributeMaxDynamicSharedMemorySize, SMEM_BYTES);
    dim3 grid(32, 32);
    conv_mma_kernel<<<grid, 256, SMEM_BYTES>>>(in, bias, out);
}

// round 15
// speedup vs baseline: 1.3082x; 1.0135x over previous
#include <cuda_runtime.h>
#include <cstdint>

// Conv2d N=32, Cin=64, 64x64, Cout=128, 3x3 s1 p1, fp32.
// Implicit GEMM on mma.sync.m16n8k8.tf32.
// R15 = R14 with a 4-buffer smem ring: prefetch distance 2 halves, ONE
// __syncthreads per iteration (trailing barrier proven unnecessary: the
// buffer staged at iter h was last read at compute(h-2), which all threads
// finished before passing iter h-1's barrier). Barriers/CTA 8 -> 4.
// B stays direct-LDG from the prep_b image. 2 CTAs/SM (reg-bound).

#define HW  64
#define CO  128
#define CIN 64

#define SB_ROW     264
#define SBQ        (36 * SB_ROW)          // 9504 floats per B quarter image
#define ROW_STRIDE 76                     // floats; 304B, 16B aligned
#define CI_STRIDE  312                    // floats; 24 mod 32; conflict-free
#define SAH        (16 * CI_STRIDE)       // 4992 floats per A half buffer
#define SMEM_BYTES (4 * SAH * 4)          // 79,872 B -> 2 CTAs/SM

__device__ __align__(16) float g_bimg[8 * SBQ];

__device__ __forceinline__ uint32_t f2tf32(float f) {
    uint32_t r; asm("cvt.rna.tf32.f32 %0, %1;" : "=r"(r) : "f"(f)); return r;
}
__device__ __forceinline__ void mma8(float c[4], const uint32_t a[4], uint2 b) {
    asm volatile(
        "mma.sync.aligned.m16n8k8.row.col.f32.tf32.tf32.f32 "
        "{%0,%1,%2,%3}, {%4,%5,%6,%7}, {%8,%9}, {%0,%1,%2,%3};"
        : "+f"(c[0]), "+f"(c[1]), "+f"(c[2]), "+f"(c[3])
        : "r"(a[0]), "r"(a[1]), "r"(a[2]), "r"(a[3]), "r"(b.x), "r"(b.y));
}
__device__ __forceinline__ uint32_t smem_u32(const void* p) {
    uint32_t a;
    asm("{ .reg .u64 t; cvta.to.shared.u64 t, %1; cvt.u32.u64 %0, t; }"
        : "=r"(a) : "l"(p));
    return a;
}

// Quarter B image: g_bimg[q][rowp = tap*4 + j][2*co + slot]
// slot0 = w[ci = q*8 + j], slot1 = w[ci = q*8 + j + 4], tf32(rna)-rounded.
__global__ void __launch_bounds__(256)
prep_b(const float* __restrict__ w)
{
    int e  = blockIdx.x * 256 + threadIdx.x;    // 0..36863
    int co = e & 127;
    int rp = e >> 7;                            // 0..287 = q*36 + rowp
    int q    = rp / 36;
    int rowp = rp - q * 36;
    int tap  = rowp >> 2;
    int jj   = rowp & 3;
    int ci0  = q * 8 + jj;
    float2 pv;
    pv.x = __uint_as_float(f2tf32(w[((size_t)ci0 * 9 + tap) * CO + co]));
    pv.y = __uint_as_float(f2tf32(w[((size_t)(ci0 + 4) * 9 + tap) * CO + co]));
    *(float2*)&g_bimg[(size_t)rp * SB_ROW + 2 * co] = pv;
}

// Stage A half: 16 ci x 4 rows x 64 cols as 16B cp.async (zfill OOB rows).
__device__ __forceinline__ void stage_half(const float* __restrict__ in,
                                           uint32_t sbase, int buf, int h,
                                           int n, int y0, int tid)
{
    const uint32_t abase = sbase + (uint32_t)(buf * SAH) * 4u;
    const float* inb = in + ((size_t)n * CIN + h * 16) * (HW * HW);
#pragma unroll
    for (int it = 0; it < 4; ++it) {
        int e   = it * 256 + tid;       // 0..1023
        int p   = e >> 4;               // ci*4 + row
        int k   = e & 15;               // 16B chunk within row
        int ci  = p >> 2;
        int row = p & 3;
        int gy  = y0 - 1 + row;
        bool ok = (unsigned)gy < (unsigned)HW;
        const float* src = inb + (((size_t)ci << 6) + (ok ? gy : 0)) * HW + (k << 2);
        uint32_t dst = abase
                     + (uint32_t)(ci * CI_STRIDE + row * ROW_STRIDE + 4 + (k << 2)) * 4u;
        uint32_t sz  = ok ? 16u : 0u;
        asm volatile("cp.async.cg.shared.global [%0], [%1], 16, %2;"
                     :: "r"(dst), "l"(src), "r"(sz) : "memory");
    }
    asm volatile("cp.async.commit_group;" ::: "memory");
}

__global__ void __launch_bounds__(256, 2)
conv_mma_kernel(const float* __restrict__ in, const float* __restrict__ bias,
                float* __restrict__ out)
{
    extern __shared__ float sm[];
    const uint32_t sbase = smem_u32(sm);

    const int tid   = threadIdx.x;
    const int lane  = tid & 31;
    const int warp  = tid >> 5;
    const int wy    = warp >> 2;        // 0..1 -> y row within tile
    const int warpN = warp & 3;         // 0..3 -> co 32-block
    const int y0    = blockIdx.x * 2;
    const int n     = blockIdx.y;

    const int r = lane >> 2;            // 0..7
    const int j = lane & 3;             // 0..3

    // Zero x-halo words (col -1 at off 3, col 64 at off 68):
    // 16ci x 4row x 2side x 4buf = 512 words.
    for (int e = tid; e < 512; e += 256) {
        int buf  = e >> 7;
        int rem  = e & 127;
        int ci   = rem >> 3;
        int row  = (rem >> 1) & 3;
        int side = rem & 1;
        sm[buf * SAH + ci * CI_STRIDE + row * ROW_STRIDE + (side ? 68 : 3)] = 0.f;
    }

    float acc[4][4][4];
#pragma unroll
    for (int mt = 0; mt < 4; ++mt)
#pragma unroll
        for (int nt = 0; nt < 4; ++nt)
#pragma unroll
            for (int qq = 0; qq < 4; ++qq) acc[mt][nt][qq] = 0.f;

    stage_half(in, sbase, 0, 0, n, y0, tid);
    stage_half(in, sbase, 1, 1, n, y0, tid);

    for (int h = 0; h < 4; ++h) {
        if (h < 2) {
            stage_half(in, sbase, (h + 2) & 3, h + 2, n, y0, tid);
            asm volatile("cp.async.wait_group 2;" ::: "memory");
        } else if (h == 2) {
            asm volatile("cp.async.wait_group 1;" ::: "memory");
        } else {
            asm volatile("cp.async.wait_group 0;" ::: "memory");
        }
        __syncthreads();   // buf h's data visible to all threads

        // ---- compute: 9 taps x 2 ksteps; A from smem, B LDG from g_bimg ----
        const float* smA = sm + (h & 3) * SAH;
        const float* __restrict__ bh = g_bimg + (size_t)(h * 2) * SBQ;
#pragma unroll
        for (int tap = 0; tap < 9; ++tap) {
            const int dy = tap / 3 - 1;
            const int dx = tap % 3 - 1;
            const float* pA = &smA[j * CI_STRIDE + (wy + dy + 1) * ROW_STRIDE
                                   + 4 + dx + r];
            const float* __restrict__ pB =
                bh + (tap * 4 + j) * SB_ROW + 2 * (warpN * 32 + r);
#pragma unroll
            for (int s = 0; s < 2; ++s) {
                const float* pAs = pA + s * 8 * CI_STRIDE;
                const float* __restrict__ pBs = pB + s * SBQ;
                uint32_t a[4][4];
#pragma unroll
                for (int mt = 0; mt < 4; ++mt) {
                    a[mt][0] = __float_as_uint(pAs[mt * 16]);
                    a[mt][1] = __float_as_uint(pAs[mt * 16 + 8]);
                    a[mt][2] = __float_as_uint(pAs[mt * 16 + 4 * CI_STRIDE]);
                    a[mt][3] = __float_as_uint(pAs[mt * 16 + 8 + 4 * CI_STRIDE]);
                }
#pragma unroll
                for (int nt = 0; nt < 4; ++nt) {
                    uint2 b = *(const uint2*)&pBs[nt * 16];
#pragma unroll
                    for (int mt = 0; mt < 4; ++mt)
                        mma8(acc[mt][nt], a[mt], b);
                }
            }
        }
        // no trailing barrier: iter h+1 stages buf (h+3)&3, which was last
        // read at compute(h-1); all threads passed THIS iter's barrier after
        // finishing that compute.
    }

    // ---- epilogue: c frag rows (r, r+8), cols (2j, 2j+1) ----
    const int y = y0 + wy;
#pragma unroll
    for (int nt = 0; nt < 4; ++nt) {
        int co = warpN * 32 + nt * 8 + 2 * j;
        float b0 = __ldg(bias + co);
        float b1 = __ldg(bias + co + 1);
        float* o0 = out + (((size_t)n * CO + co) * HW + y) * HW;
#pragma unroll
        for (int mt = 0; mt < 4; ++mt) {
            int x = mt * 16 + r;
            o0[x]               = acc[mt][nt][0] + b0;
            o0[HW * HW + x]     = acc[mt][nt][1] + b1;
            o0[x + 8]           = acc[mt][nt][2] + b0;
            o0[HW * HW + x + 8] = acc[mt][nt][3] + b1;
        }
    }
}

extern "C" void kernel_launch(void* const* d_in, const int* in_sizes, int n_in,
                              void* d_out, int out_size)
{
    const float* in   = (const float*)d_in[0];
    const float* w    = (const float*)d_in[1];
    const float* bias = (const float*)d_in[2];
    float* out        = (float*)d_out;

    prep_b<<<144, 256>>>(w);

    cudaFuncSetAttribute(conv_mma_kernel,
                         cudaFuncAttributeMaxDynamicSharedMemorySize, SMEM_BYTES);
    dim3 grid(32, 32);
    conv_mma_kernel<<<grid, 256, SMEM_BYTES>>>(in, bias, out);
}

// round 16
// speedup vs baseline: 1.4759x; 1.1282x over previous
#include <cuda_runtime.h>
#include <cuda_fp16.h>
#include <cstdint>

// Conv2d N=32, Cin=64, 64x64, Cout=128, 3x3 s1 p1, fp32.
// Implicit GEMM on mma.sync.m16n8k16.f16 (fp32 accumulate).
// R16 = R15 pipeline with tf32 -> fp16: same 10-bit mantissa, 2x MACs/HMMA,
// half the L1 bytes on A and B. prep_a builds a ci-paired fp16 image of the
// input once per launch (so A staging stays raw 16B cp.async); prep_b builds
// fp16 b-frag quads {B[2j],B[2j+1],B[2j+8],B[2j+9]} so one LDG.64 = b0,b1.
// 4-buffer smem ring over 4 halves of 16 ci, 1 barrier/iter, 2 CTAs/SM.

#define HW  64
#define CO  128
#define CIN 64

#define ROW_STRIDE 72                     // fp16x2 words; 288B, 16B aligned
#define PAIR_STRIDE 296                   // words; 296 mod 32 = 8 -> banks 8j+r
#define SAH        (8 * PAIR_STRIDE)      // 2368 words per A half (8 ci-pairs)
#define SMEM_BYTES (4 * SAH * 4)          // 37,888 B -> 2 CTAs/SM

// A image: [n][pair=32][y=64][x=64] of fp16x2 (ci 2p, 2p+1 packed)
__device__ __align__(16) uint32_t g_aimg[32u * 32u * 64u * 64u];
// B image: [(h*9+tap)*4+j][co=128] of uint2 = {B[2j],B[2j+1],B[2j+8],B[2j+9]}
__device__ __align__(16) uint2 g_bimg[4 * 9 * 4 * 128];

__device__ __forceinline__ void mma16(float c[4], const uint32_t a[4], uint2 b) {
    asm volatile(
        "mma.sync.aligned.m16n8k16.row.col.f32.f16.f16.f32 "
        "{%0,%1,%2,%3}, {%4,%5,%6,%7}, {%8,%9}, {%0,%1,%2,%3};"
        : "+f"(c[0]), "+f"(c[1]), "+f"(c[2]), "+f"(c[3])
        : "r"(a[0]), "r"(a[1]), "r"(a[2]), "r"(a[3]), "r"(b.x), "r"(b.y));
}
__device__ __forceinline__ uint32_t smem_u32(const void* p) {
    uint32_t a;
    asm("{ .reg .u64 t; cvta.to.shared.u64 t, %1; cvt.u32.u64 %0, t; }"
        : "=r"(a) : "l"(p));
    return a;
}

// Pack input planes (2p, 2p+1) into fp16x2 image. 4,194,304 elements.
__global__ void __launch_bounds__(256)
prep_a(const float* __restrict__ in)
{
    uint32_t e = blockIdx.x * 256u + threadIdx.x;
    uint32_t n  = e >> 17;
    uint32_t p  = (e >> 12) & 31;
    uint32_t yx = e & 4095;
    const float* base = in + ((size_t)n * CIN + 2 * p) * (HW * HW) + yx;
    __half2 h = __floats2half2_rn(base[0], base[HW * HW]);
    g_aimg[e] = *(uint32_t*)&h;
}

// b-frag quads, rna fp16. 18432 elements.
__global__ void __launch_bounds__(256)
prep_b(const float* __restrict__ w)
{
    uint32_t e  = blockIdx.x * 256u + threadIdx.x;   // 0..18431
    uint32_t co = e & 127;
    uint32_t rp = e >> 7;                            // ((h*9+tap)*4+j)
    uint32_t j  = rp & 3;
    uint32_t ht = rp >> 2;                           // h*9 + tap
    uint32_t h  = ht / 9;
    uint32_t tap = ht - h * 9;
    uint32_t ci0 = h * 16 + 2 * j;                   // k = 2j, 2j+1
    uint32_t ci2 = ci0 + 8;                          // k = 2j+8, 2j+9
    __half2 lo = __floats2half2_rn(w[((size_t)ci0 * 9 + tap) * CO + co],
                                   w[((size_t)(ci0 + 1) * 9 + tap) * CO + co]);
    __half2 hi = __floats2half2_rn(w[((size_t)ci2 * 9 + tap) * CO + co],
                                   w[((size_t)(ci2 + 1) * 9 + tap) * CO + co]);
    uint2 v;
    v.x = *(uint32_t*)&lo;
    v.y = *(uint32_t*)&hi;
    g_bimg[rp * 128 + co] = v;
}

// Stage A half h: 8 ci-pairs x 4 rows x 64 x (16B chunks, zfill OOB rows).
__device__ __forceinline__ void stage_half(uint32_t sbase, int buf, int h,
                                           int n, int y0, int tid)
{
    const uint32_t abase = sbase + (uint32_t)(buf * SAH) * 4u;
#pragma unroll
    for (int it = 0; it < 2; ++it) {
        int e   = it * 256 + tid;       // 0..511
        int pp  = e >> 6;               // ci-pair 0..7
        int row = (e >> 4) & 3;
        int k   = e & 15;               // 16B chunk within row
        int gy  = y0 - 1 + row;
        bool ok = (unsigned)gy < (unsigned)HW;
        const uint32_t* src = g_aimg
            + ((((size_t)n * 32 + h * 8 + pp) << 6) + (ok ? gy : 0)) * 64
            + (k << 2);
        uint32_t dst = abase
            + (uint32_t)(pp * PAIR_STRIDE + row * ROW_STRIDE + 4 + (k << 2)) * 4u;
        uint32_t sz = ok ? 16u : 0u;
        asm volatile("cp.async.cg.shared.global [%0], [%1], 16, %2;"
                     :: "r"(dst), "l"(src), "r"(sz) : "memory");
    }
    asm volatile("cp.async.commit_group;" ::: "memory");
}

__global__ void __launch_bounds__(256, 2)
conv_mma_kernel(const float* __restrict__ bias, float* __restrict__ out)
{
    extern __shared__ uint32_t sm[];
    const uint32_t sbase = smem_u32(sm);

    const int tid   = threadIdx.x;
    const int lane  = tid & 31;
    const int warp  = tid >> 5;
    const int wy    = warp >> 2;        // 0..1 -> y row within tile
    const int warpN = warp & 3;         // 0..3 -> co 32-block
    const int y0    = blockIdx.x * 2;
    const int n     = blockIdx.y;

    const int r = lane >> 2;            // 0..7
    const int j = lane & 3;             // 0..3

    // Zero x-halo words (x=-1 at word 3, x=64 at word 68):
    // 8pair x 4row x 2side x 4buf = 256 words, one per thread.
    {
        int buf  = tid >> 6;
        int rem  = tid & 63;
        int pp   = rem >> 3;
        int row  = (rem >> 1) & 3;
        int side = rem & 1;
        sm[buf * SAH + pp * PAIR_STRIDE + row * ROW_STRIDE + (side ? 68 : 3)] = 0u;
    }

    float acc[4][4][4];
#pragma unroll
    for (int mt = 0; mt < 4; ++mt)
#pragma unroll
        for (int nt = 0; nt < 4; ++nt)
#pragma unroll
            for (int qq = 0; qq < 4; ++qq) acc[mt][nt][qq] = 0.f;

    stage_half(sbase, 0, 0, n, y0, tid);
    stage_half(sbase, 1, 1, n, y0, tid);

    for (int h = 0; h < 4; ++h) {
        if (h < 2) {
            stage_half(sbase, (h + 2) & 3, h + 2, n, y0, tid);
            asm volatile("cp.async.wait_group 2;" ::: "memory");
        } else if (h == 2) {
            asm volatile("cp.async.wait_group 1;" ::: "memory");
        } else {
            asm volatile("cp.async.wait_group 0;" ::: "memory");
        }
        __syncthreads();   // buf h's data visible to all threads

        // ---- compute: 9 taps x 1 k16-step; A smem LDS.32, B LDG.64 ----
        const uint32_t* smA = sm + (h & 3) * SAH;
        const uint2* __restrict__ bh = g_bimg + (size_t)(h * 9) * 4 * 128;
#pragma unroll
        for (int tap = 0; tap < 9; ++tap) {
            const int dy = tap / 3 - 1;
            const int dx = tap % 3 - 1;
            const uint32_t* pAs = &smA[j * PAIR_STRIDE
                                       + (wy + dy + 1) * ROW_STRIDE + 4 + dx + r];
            const uint2* __restrict__ pBs =
                bh + (tap * 4 + j) * 128 + warpN * 32 + r;
            uint32_t a[4][4];
#pragma unroll
            for (int mt = 0; mt < 4; ++mt) {
                a[mt][0] = pAs[mt * 16];                       // (m=r,    k 2j..)
                a[mt][1] = pAs[mt * 16 + 8];                   // (m=r+8)
                a[mt][2] = pAs[mt * 16 + 4 * PAIR_STRIDE];     // (m=r,    k 2j+8..)
                a[mt][3] = pAs[mt * 16 + 8 + 4 * PAIR_STRIDE]; // (m=r+8)
            }
#pragma unroll
            for (int nt = 0; nt < 4; ++nt) {
                uint2 b = pBs[nt * 8];
#pragma unroll
                for (int mt = 0; mt < 4; ++mt)
                    mma16(acc[mt][nt], a[mt], b);
            }
        }
        // no trailing barrier (4-buffer ring; see R15 proof)
    }

    // ---- epilogue: c frag rows (r, r+8), cols (2j, 2j+1) ----
    const int y = y0 + wy;
#pragma unroll
    for (int nt = 0; nt < 4; ++nt) {
        int co = warpN * 32 + nt * 8 + 2 * j;
        float b0 = __ldg(bias + co);
        float b1 = __ldg(bias + co + 1);
        float* o0 = out + (((size_t)n * CO + co) * HW + y) * HW;
#pragma unroll
        for (int mt = 0; mt < 4; ++mt) {
            int x = mt * 16 + r;
            o0[x]               = acc[mt][nt][0] + b0;
            o0[HW * HW + x]     = acc[mt][nt][1] + b1;
            o0[x + 8]           = acc[mt][nt][2] + b0;
            o0[HW * HW + x + 8] = acc[mt][nt][3] + b1;
        }
    }
}

extern "C" void kernel_launch(void* const* d_in, const int* in_sizes, int n_in,
                              void* d_out, int out_size)
{
    const float* in   = (const float*)d_in[0];
    const float* w    = (const float*)d_in[1];
    const float* bias = (const float*)d_in[2];
    float* out        = (float*)d_out;

    prep_a<<<16384, 256>>>(in);
    prep_b<<<72, 256>>>(w);

    cudaFuncSetAttribute(conv_mma_kernel,
                         cudaFuncAttributeMaxDynamicSharedMemorySize, SMEM_BYTES);
    dim3 grid(32, 32);
    conv_mma_kernel<<<grid, 256, SMEM_BYTES>>>(bias, out);
}

// round 17
// speedup vs baseline: 1.5788x; 1.0697x over previous
#include <cuda_runtime.h>
#include <cuda_fp16.h>
#include <cstdint>

// Conv2d N=32, Cin=64, 64x64, Cout=128, 3x3 s1 p1, fp32.
// Implicit GEMM on mma.sync.m16n8k16.f16 (fp32 accumulate).
// R17 = R16 with a k-contiguous A image [n][h][y][x][16ci] so A-frags load
// via ldmatrix.m8n8.x4 (1 LDSM replaces 4 LDS.32; 16 -> 4 per tap).
// Smem row stride 48B -> LDSM banks (12*l mod 32) all distinct.
// B path unchanged (prep_b quads + direct LDG.64). 4-buffer ring, 2 CTAs/SM.

#define HW  64
#define CO  128
#define CIN 64

#define XSTRIDE    48                     // bytes per x row (32B data + 16B pad)
#define YSTRIDE    (66 * XSTRIDE)         // 3168 B
#define SAH_BYTES  (4 * YSTRIDE)          // 12672 B per A half buffer
#define SMEM_BYTES (4 * SAH_BYTES)        // 50688 B -> 2 CTAs/SM

// A image: [n][h=4][y=64][x=64][16 ci halves] = 8 uint32 words per pixel
__device__ __align__(16) uint32_t g_aimg[32u * 4u * 64u * 64u * 8u];
// B image: [(h*9+tap)*4+j][co=128] of uint2 = {B[2j],B[2j+1],B[2j+8],B[2j+9]}
__device__ __align__(16) uint2 g_bimg[4 * 9 * 4 * 128];

__device__ __forceinline__ void mma16(float c[4], const uint32_t a[4], uint2 b) {
    asm volatile(
        "mma.sync.aligned.m16n8k16.row.col.f32.f16.f16.f32 "
        "{%0,%1,%2,%3}, {%4,%5,%6,%7}, {%8,%9}, {%0,%1,%2,%3};"
        : "+f"(c[0]), "+f"(c[1]), "+f"(c[2]), "+f"(c[3])
        : "r"(a[0]), "r"(a[1]), "r"(a[2]), "r"(a[3]), "r"(b.x), "r"(b.y));
}
__device__ __forceinline__ void ldsm4(uint32_t a[4], uint32_t addr) {
    asm volatile("ldmatrix.sync.aligned.m8n8.x4.shared.b16 {%0,%1,%2,%3}, [%4];"
                 : "=r"(a[0]), "=r"(a[1]), "=r"(a[2]), "=r"(a[3]) : "r"(addr));
}
__device__ __forceinline__ uint32_t smem_u32(const void* p) {
    uint32_t a;
    asm("{ .reg .u64 t; cvta.to.shared.u64 t, %1; cvt.u32.u64 %0, t; }"
        : "=r"(a) : "l"(p));
    return a;
}

// Build k-contiguous A image: thread = one (n,h,y,x); 16 coalesced plane
// loads -> 8 half2 -> 2 uint4 stores.
__global__ void __launch_bounds__(256)
prep_a(const float* __restrict__ in)
{
    uint32_t e  = blockIdx.x * 256u + threadIdx.x;   // 0..524287
    uint32_t n  = e >> 14;
    uint32_t h  = (e >> 12) & 3;
    uint32_t yx = e & 4095;
    const float* base = in + ((size_t)(n * CIN + h * 16)) * (HW * HW) + yx;
    uint32_t wds[8];
#pragma unroll
    for (int k = 0; k < 8; ++k) {
        __half2 v = __floats2half2_rn(base[(2 * k) * HW * HW],
                                      base[(2 * k + 1) * HW * HW]);
        wds[k] = *(uint32_t*)&v;
    }
    uint4* dst = (uint4*)(g_aimg + (size_t)e * 8);
    dst[0] = make_uint4(wds[0], wds[1], wds[2], wds[3]);
    dst[1] = make_uint4(wds[4], wds[5], wds[6], wds[7]);
}

// b-frag quads, rn fp16 (unchanged from R16).
__global__ void __launch_bounds__(256)
prep_b(const float* __restrict__ w)
{
    uint32_t e  = blockIdx.x * 256u + threadIdx.x;   // 0..18431
    uint32_t co = e & 127;
    uint32_t rp = e >> 7;                            // ((h*9+tap)*4+j)
    uint32_t j  = rp & 3;
    uint32_t ht = rp >> 2;                           // h*9 + tap
    uint32_t h  = ht / 9;
    uint32_t tap = ht - h * 9;
    uint32_t ci0 = h * 16 + 2 * j;                   // k = 2j, 2j+1
    uint32_t ci2 = ci0 + 8;                          // k = 2j+8, 2j+9
    __half2 lo = __floats2half2_rn(w[((size_t)ci0 * 9 + tap) * CO + co],
                                   w[((size_t)(ci0 + 1) * 9 + tap) * CO + co]);
    __half2 hi = __floats2half2_rn(w[((size_t)ci2 * 9 + tap) * CO + co],
                                   w[((size_t)(ci2 + 1) * 9 + tap) * CO + co]);
    uint2 v;
    v.x = *(uint32_t*)&lo;
    v.y = *(uint32_t*)&hi;
    g_bimg[rp * 128 + co] = v;
}

// Stage A half h: 4 y-rows x 64 x x 2 16B-chunks (zfill OOB rows).
__device__ __forceinline__ void stage_half(uint32_t sbase, int buf, int h,
                                           int n, int y0, int tid)
{
    const uint32_t abase = sbase + (uint32_t)buf * SAH_BYTES;
#pragma unroll
    for (int it = 0; it < 2; ++it) {
        int e   = it * 256 + tid;       // 0..511
        int row = e >> 7;               // 0..3
        int rem = e & 127;
        int x   = rem >> 1;             // 0..63
        int ch  = rem & 1;              // 16B chunk
        int gy  = y0 - 1 + row;
        bool ok = (unsigned)gy < (unsigned)HW;
        const uint32_t* src = g_aimg
            + (((size_t)(n * 4 + h) * 64 + (ok ? gy : 0)) * 64 + x) * 8 + ch * 4;
        uint32_t dst = abase
            + (uint32_t)(row * YSTRIDE + (1 + x) * XSTRIDE + ch * 16);
        uint32_t sz = ok ? 16u : 0u;
        asm volatile("cp.async.cg.shared.global [%0], [%1], 16, %2;"
                     :: "r"(dst), "l"(src), "r"(sz) : "memory");
    }
    asm volatile("cp.async.commit_group;" ::: "memory");
}

__global__ void __launch_bounds__(256, 2)
conv_mma_kernel(const float* __restrict__ bias, float* __restrict__ out)
{
    extern __shared__ uint32_t sm[];
    const uint32_t sbase = smem_u32(sm);

    const int tid   = threadIdx.x;
    const int lane  = tid & 31;
    const int warp  = tid >> 5;
    const int wy    = warp >> 2;        // 0..1 -> y row within tile
    const int warpN = warp & 3;         // 0..3 -> co 32-block
    const int y0    = blockIdx.x * 2;
    const int n     = blockIdx.y;

    const int r = lane >> 2;            // 0..7
    const int j = lane & 3;             // 0..3

    // ldmatrix lane offset: lanes 0-15 -> rows m=0..15 k-half 0,
    // lanes 16-31 -> rows m=0..15 k-half 1.
    const uint32_t laneoff = (uint32_t)((lane & 15) * XSTRIDE + (lane >> 4) * 16);

    // Zero x-halo rows (x index 0 and 65): 4buf x 4row x 2side x 2chunk = 64.
    if (tid < 64) {
        int buf  = tid >> 4;
        int rem  = tid & 15;
        int row  = rem >> 2;
        int side = (rem >> 1) & 1;
        int ch   = rem & 1;
        uint32_t off = (uint32_t)buf * SAH_BYTES + row * YSTRIDE
                     + (side ? 65 : 0) * XSTRIDE + ch * 16;
        *(uint4*)((char*)sm + off) = make_uint4(0, 0, 0, 0);
    }

    float acc[4][4][4];
#pragma unroll
    for (int mt = 0; mt < 4; ++mt)
#pragma unroll
        for (int nt = 0; nt < 4; ++nt)
#pragma unroll
            for (int qq = 0; qq < 4; ++qq) acc[mt][nt][qq] = 0.f;

    stage_half(sbase, 0, 0, n, y0, tid);
    stage_half(sbase, 1, 1, n, y0, tid);

    for (int h = 0; h < 4; ++h) {
        if (h < 2) {
            stage_half(sbase, (h + 2) & 3, h + 2, n, y0, tid);
            asm volatile("cp.async.wait_group 2;" ::: "memory");
        } else if (h == 2) {
            asm volatile("cp.async.wait_group 1;" ::: "memory");
        } else {
            asm volatile("cp.async.wait_group 0;" ::: "memory");
        }
        __syncthreads();   // buf h's data visible to all threads

        // ---- compute: 9 taps; per tap 4 LDSM.x4 (A) + 4 LDG.64 (B) + 16 MMA
        const uint32_t abuf = sbase + (uint32_t)(h & 3) * SAH_BYTES;
        const uint2* __restrict__ bh = g_bimg + (size_t)(h * 9) * 4 * 128;
#pragma unroll
        for (int tap = 0; tap < 9; ++tap) {
            const int dy = tap / 3 - 1;
            const int dx = tap % 3 - 1;
            uint32_t rowbase = abuf
                + (uint32_t)((wy + 1 + dy) * YSTRIDE + (1 + dx) * XSTRIDE)
                + laneoff;
            const uint2* __restrict__ pBs =
                bh + (tap * 4 + j) * 128 + warpN * 32 + r;
            uint32_t a[4][4];
#pragma unroll
            for (int mt = 0; mt < 4; ++mt)
                ldsm4(a[mt], rowbase + mt * (16 * XSTRIDE));
#pragma unroll
            for (int nt = 0; nt < 4; ++nt) {
                uint2 b = pBs[nt * 8];
#pragma unroll
                for (int mt = 0; mt < 4; ++mt)
                    mma16(acc[mt][nt], a[mt], b);
            }
        }
        // no trailing barrier (4-buffer ring; see R15 proof)
    }

    // ---- epilogue: c frag rows (r, r+8), cols (2j, 2j+1) ----
    const int y = y0 + wy;
#pragma unroll
    for (int nt = 0; nt < 4; ++nt) {
        int co = warpN * 32 + nt * 8 + 2 * j;
        float b0 = __ldg(bias + co);
        float b1 = __ldg(bias + co + 1);
        float* o0 = out + (((size_t)n * CO + co) * HW + y) * HW;
#pragma unroll
        for (int mt = 0; mt < 4; ++mt) {
            int x = mt * 16 + r;
            o0[x]               = acc[mt][nt][0] + b0;
            o0[HW * HW + x]     = acc[mt][nt][1] + b1;
            o0[x + 8]           = acc[mt][nt][2] + b0;
            o0[HW * HW + x + 8] = acc[mt][nt][3] + b1;
        }
    }
}

extern "C" void kernel_launch(void* const* d_in, const int* in_sizes, int n_in,
                              void* d_out, int out_size)
{
    const float* in   = (const float*)d_in[0];
    const float* w    = (const float*)d_in[1];
    const float* bias = (const float*)d_in[2];
    float* out        = (float*)d_out;

    prep_a<<<2048, 256>>>(in);
    prep_b<<<72, 256>>>(w);

    cudaFuncSetAttribute(conv_mma_kernel,
                         cudaFuncAttributeMaxDynamicSharedMemorySize, SMEM_BYTES);
    dim3 grid(32, 32);
    conv_mma_kernel<<<grid, 256, SMEM_BYTES>>>(bias, out);
}